// round 4
// baseline (speedup 1.0000x reference)
#include <cuda_runtime.h>
#include <float.h>
#include <math.h>

// CropRoi: f (4,64,32,32,32) f32; proposals (96,8) f32; out (96,64,7,7,7) f32.
// Box: c0 = max(floor((c-s/2)/4),0), c1 = min(ceil((c+s/2)/4),32).
// Given setup ranges, L = c1-c0 is in [2,13]; every adaptive window
// [i*L/7, ceil((i+1)L/7)) has size 1..3 and is in-range -> plain max.
//
// Launch 1 (precompute, N blocks x 352): per proposal
//   g_meta[n] = (base element offset for ch0, nrows = Ld*Lh, Lw)
//   g_rows[n][r] = packed (f row offset | smem row offset << 16)
//   g_desc[n][o] = packed smem-relative bin window (fixed strides 224/16/1)
// Launch 2 (pool, grid N x 64, 352 thr): warps stage box rows coalesced into
//   a 14x14x16 smem tile (no div/mod, no box math), sync, one thread per bin
//   does ~2.2 LDS + fmax + 1 coalesced STG.

#define RBINS 7
#define NBINS (RBINS * RBINS * RBINS)   // 343
#define FDIM 32
#define MAXN 128
#define MAXROWS 176                      // >= 13*13, padded
#define TD_STRIDE 224                    // 14*16, smem d-stride
#define TH_STRIDE 16                     // smem h-stride

__device__ int4 g_meta[MAXN];            // x=base, y=nrows, z=Lw
__device__ int  g_rows[MAXN * MAXROWS];
__device__ int  g_desc[MAXN * NBINS];

__global__ void precompute_kernel(const float* __restrict__ props)
{
    const int n = blockIdx.x;
    const int o = threadIdx.x;
    const float* p = props + n * 8;

    int c0[3], L[3];
#pragma unroll
    for (int ax = 0; ax < 3; ++ax) {
        const float ce = p[2 + ax], si = p[5 + ax];
        int lo = (int)floorf((ce - si * 0.5f) * 0.25f);
        int hi = (int)ceilf ((ce + si * 0.5f) * 0.25f);
        lo = max(lo, 0); hi = min(hi, FDIM);
        c0[ax] = lo;
        L[ax]  = max(hi - lo, 0);
    }
    const int Ld = L[0], Lh = L[1], Lw = L[2];
    const int nrows = Ld * Lh;

    if (o == 0) {
        const int b = (int)p[0];
        const int base = ((b * 64) << 15) +
                         ((c0[0] * FDIM + c0[1]) * FDIM + c0[2]);
        g_meta[n] = make_int4(base, nrows, Lw, 0);
    }

    // row plan: r -> (d, h)
    if (o < nrows) {
        const int d = o / Lh;          // precompute only: div is fine here
        const int h = o - d * Lh;
        const int src = d * (FDIM * FDIM) + h * FDIM;     // <= 14 bits
        const int dst = d * TD_STRIDE + h * TH_STRIDE;    // <= 12 bits
        g_rows[n * MAXROWS + o] = src | (dst << 16);
    }

    // bin descriptors (smem-relative, fixed strides)
    if (o < NBINS) {
        const int k = o % RBINS;
        const int j = (o / RBINS) % RBINS;
        const int i = o / (RBINS * RBINS);

        const int ds = (i * Ld) / RBINS, de = ((i + 1) * Ld + RBINS - 1) / RBINS;
        const int hs = (j * Lh) / RBINS, he = ((j + 1) * Lh + RBINS - 1) / RBINS;
        const int ws = (k * Lw) / RBINS, we = ((k + 1) * Lw + RBINS - 1) / RBINS;

        const int start = ds * TD_STRIDE + hs * TH_STRIDE + ws;   // <= 12 bits
        const int nd = de - ds - 1, nh = he - hs - 1, nw = we - ws - 1; // 0..2
        g_desc[n * NBINS + o] = start | (nd << 12) | (nh << 14) | (nw << 16);
    }
}

__global__ __launch_bounds__(352, 5)
void pool_kernel(const float* __restrict__ f, float* __restrict__ out)
{
    const int n = blockIdx.x;   // proposal
    const int c = blockIdx.y;   // channel
    const int tid  = threadIdx.x;
    const int lane = tid & 31;
    const int wid  = tid >> 5;  // 0..10

    __shared__ float tile[14 * TD_STRIDE];   // 3136 floats = 12544 B

    const int4 meta = g_meta[n];             // uniform per block
    const float* src = f + meta.x + (c << 15);

    // ---- stage box rows, coalesced, no div/mod ----
    for (int r = wid; r < meta.y; r += 11) {
        const int rd = g_rows[n * MAXROWS + r];
        if (lane < meta.z)
            tile[(rd >> 16) + lane] = src[(rd & 0xFFFF) + lane];
    }
    __syncthreads();

    // ---- pool from smem, one thread per bin ----
    if (tid < NBINS) {
        const int desc  = g_desc[n * NBINS + tid];
        const int start =  desc        & 0xFFF;
        const int nd    = (desc >> 12) & 3;
        const int nh    = (desc >> 14) & 3;
        const int nw    = (desc >> 16) & 3;

        float m = -FLT_MAX;
        const float* t0 = tile + start;
        for (int d = 0; d <= nd; ++d) {
            const float* td = t0 + d * TD_STRIDE;
            for (int h = 0; h <= nh; ++h) {
                const float* th = td + h * TH_STRIDE;
                for (int w = 0; w <= nw; ++w)
                    m = fmaxf(m, th[w]);
            }
        }
        out[(size_t)(n * 64 + c) * NBINS + tid] = m;
    }
}

extern "C" void kernel_launch(void* const* d_in, const int* in_sizes, int n_in,
                              void* d_out, int out_size)
{
    const float* f     = (const float*)d_in[0];
    const float* props = (const float*)d_in[2];
    float* out = (float*)d_out;

    const int N = in_sizes[2] / 8;   // 96

    precompute_kernel<<<N, 352>>>(props);
    pool_kernel<<<dim3(N, 64), 352>>>(f, out);
}

// round 5
// speedup vs baseline: 1.2013x; 1.2013x over previous
#include <cuda_runtime.h>
#include <float.h>
#include <math.h>

// CropRoi: f (4,64,32,32,32) f32; proposals (96,8) f32; out (96,64,7,7,7) f32.
// Box: c0 = max(floor((c-s/2)/4),0), c1 = min(ceil((c+s/2)/4),32); L in [2,13].
// Adaptive windows per axis have size 1..3, always in-range -> plain max.
//
// Structure: an f row (fixed d,h) is 32 floats = one aligned 128B line.
// Phase 1: warp loads a full row (lane = w, ONE wavefront), pools the 7
//          w-windows with 3 shuffles, stores 7 row-maxes to a smem pyramid.
//          Row plan is prefetched lane-vectorized and distributed via shfl.
// Phase 2: one thread per bin maxes <=3x3 pyramid entries (LDS), coalesced STG.
// All box math / div / mod lives in a tiny precompute kernel (96 blocks).

#define RBINS 7
#define NBINS 343
#define FDIM 32
#define MAXN 128
#define MAXROWS 176          // >= 13*13
#define PH 8                 // pyramid k-stride
#define PD 112               // pyramid d-stride (14*8)

__device__ int2 g_meta[MAXN];             // x = base elem offset (ch0), y = nrows
__device__ int  g_wwin[MAXN * 8];         // per k: s0 | s1<<8 | s2<<16 (abs w lanes)
__device__ int  g_rows[MAXN * MAXROWS];   // src row offset | pyramid dst << 16
__device__ int  g_desc[MAXN * NBINS];     // pyr start (11b) | nd<<11 | nh<<13

__global__ void precompute_kernel(const float* __restrict__ props)
{
    const int n = blockIdx.x;
    const int o = threadIdx.x;
    const float* p = props + n * 8;

    int c0[3], L[3];
#pragma unroll
    for (int ax = 0; ax < 3; ++ax) {
        const float ce = p[2 + ax], si = p[5 + ax];
        int lo = (int)floorf((ce - si * 0.5f) * 0.25f);
        int hi = (int)ceilf ((ce + si * 0.5f) * 0.25f);
        lo = max(lo, 0); hi = min(hi, FDIM);
        c0[ax] = lo;
        L[ax]  = max(hi - lo, 0);
    }
    const int Ld = L[0], Lh = L[1], Lw = L[2];
    const int nrows = Ld * Lh;

    if (o == 0) {
        const int b = (int)p[0];
        g_meta[n] = make_int2((b * 64) << 15, nrows);
    }

    if (o < 8) {                       // w-window shuffle sources (abs lane idx)
        const int k = min(o, 6);
        const int s = c0[2] + (k * Lw) / RBINS;
        const int e = c0[2] + ((k + 1) * Lw + RBINS - 1) / RBINS;
        const int s0 = s, s2 = e - 1, s1 = min(s0 + 1, s2);
        g_wwin[n * 8 + o] = s0 | (s1 << 8) | (s2 << 16);
    }

    if (o < nrows) {                   // row plan
        const int d = o / Lh;
        const int h = o - d * Lh;
        const int src = (c0[0] + d) * (FDIM * FDIM) + (c0[1] + h) * FDIM; // 15b
        const int dst = d * PD + h * PH;                                   // 11b
        g_rows[n * MAXROWS + o] = src | (dst << 16);
    }

    if (o < NBINS) {                   // phase-2 bin descriptors
        const int k = o % RBINS;
        const int j = (o / RBINS) % RBINS;
        const int i = o / (RBINS * RBINS);

        const int ds = (i * Ld) / RBINS, de = ((i + 1) * Ld + RBINS - 1) / RBINS;
        const int hs = (j * Lh) / RBINS, he = ((j + 1) * Lh + RBINS - 1) / RBINS;

        const int start = ds * PD + hs * PH + k;        // <= 1566, 11 bits
        const int nd = de - ds - 1, nh = he - hs - 1;   // 0..2
        g_desc[n * NBINS + o] = start | (nd << 11) | (nh << 13);
    }
}

__global__ __launch_bounds__(352, 5)
void pool_kernel(const float* __restrict__ f, float* __restrict__ out)
{
    const int n = blockIdx.x;
    const int c = blockIdx.y;
    const int tid  = threadIdx.x;
    const int lane = tid & 31;
    const int wid  = tid >> 5;          // 0..10

    __shared__ float pyr[14 * PD];      // 1568 floats = 6272 B

    const int2 meta = g_meta[n];
    const float* src = f + meta.x + (c << 15);

    // shuffle sources for this lane's w-window (lanes 0..6 meaningful)
    const int wp = g_wwin[n * 8 + (lane & 7)];
    const int s0 =  wp        & 0xFF;
    const int s1 = (wp >>  8) & 0xFF;
    const int s2 = (wp >> 16) & 0xFF;

    // prefetch this warp's row plan: lane 'it' holds plan for iteration 'it'
    const int plan = g_rows[n * MAXROWS + min(wid + lane * 11, MAXROWS - 1)];
    const int nit = (meta.y - wid + 10) / 11;   // rows wid, wid+11, ...

    for (int it = 0; it < nit; ++it) {
        const int rd = __shfl_sync(0xFFFFFFFFu, plan, it);
        const float v = src[(rd & 0xFFFF) + lane];      // full row, 1 wavefront
        const float a = __shfl_sync(0xFFFFFFFFu, v, s0);
        const float b = __shfl_sync(0xFFFFFFFFu, v, s1);
        const float d2 = __shfl_sync(0xFFFFFFFFu, v, s2);
        if (lane < RBINS)
            pyr[(rd >> 16) + lane] = fmaxf(fmaxf(a, b), d2);
    }
    __syncthreads();

    if (tid < NBINS) {
        const int dsc = g_desc[n * NBINS + tid];
        const int st =  dsc        & 0x7FF;
        const int nd = (dsc >> 11) & 3;
        const int nh = (dsc >> 13) & 3;

        float m = -FLT_MAX;
        for (int d = 0; d <= nd; ++d)
            for (int h = 0; h <= nh; ++h)
                m = fmaxf(m, pyr[st + d * PD + h * PH]);

        out[(size_t)(n * 64 + c) * NBINS + tid] = m;
    }
}

extern "C" void kernel_launch(void* const* d_in, const int* in_sizes, int n_in,
                              void* d_out, int out_size)
{
    const float* f     = (const float*)d_in[0];
    const float* props = (const float*)d_in[2];
    float* out = (float*)d_out;

    const int N = in_sizes[2] / 8;   // 96

    precompute_kernel<<<N, 352>>>(props);
    pool_kernel<<<dim3(N, 64), 352>>>(f, out);
}

// round 6
// speedup vs baseline: 1.3939x; 1.1604x over previous
#include <cuda_runtime.h>
#include <float.h>
#include <math.h>

// CropRoi: f (4,64,32,32,32) f32; proposals (96,8) f32; out (96,64,7,7,7) f32.
// Box: c0 = max(floor((c-s/2)/4),0), c1 = min(ceil((c+s/2)/4),32); L in [2,13].
// Adaptive windows per axis: size 1..3, always in-range -> plain max.
//
// pool kernel, grid (96, 8): 8 channels per block.
// Phase 1: lanes 0..27 = 7 w-bins x 4 padded taps (w = min(s+t, e-1)); one LDG
//   per (row, channel) hits a single 128B line (1 wavefront); 2 shfl.xor reduce
//   each quad to the bin max; lane 4k stores to a smem pyramid [ch][d][h][k].
// Phase 2: one thread per bin: desc decoded once, 8 channels of ~3.7 LDS + STG.
// All box math / div / mod lives in the tiny precompute kernel.

#define RBINS 7
#define NBINS 343
#define FDIM 32
#define MAXN 128
#define MAXROWS 176          // >= 13*13 (+ padding for clamped prefetch)
#define PH 7                 // pyramid h-stride
#define PD 98                // pyramid d-stride (14*7)
#define PC 1372              // pyramid channel stride (14*98)
#define CH 8                 // channels per block

__device__ int2 g_meta[MAXN];             // x = batch base offset (ch0), y = nrows
__device__ int  g_wsrc[MAXN * 32];        // per-lane absolute w source
__device__ int  g_rows[MAXN * MAXROWS];   // src row offset | pyramid dst << 16
__device__ int  g_desc[MAXN * NBINS];     // pyr start (11b) | nd<<11 | nh<<13

__global__ void precompute_kernel(const float* __restrict__ props)
{
    const int n = blockIdx.x;
    const int o = threadIdx.x;
    const float* p = props + n * 8;

    int c0[3], L[3];
#pragma unroll
    for (int ax = 0; ax < 3; ++ax) {
        const float ce = p[2 + ax], si = p[5 + ax];
        int lo = (int)floorf((ce - si * 0.5f) * 0.25f);
        int hi = (int)ceilf ((ce + si * 0.5f) * 0.25f);
        lo = max(lo, 0); hi = min(hi, FDIM);
        c0[ax] = lo;
        L[ax]  = max(hi - lo, 0);
    }
    const int Ld = L[0], Lh = L[1], Lw = L[2];
    const int nrows = Ld * Lh;

    if (o == 0) {
        const int b = (int)p[0];
        g_meta[n] = make_int2((b * 64) << 15, nrows);
    }

    if (o < 32) {                    // padded w-window taps, absolute w coord
        const int k = min(o >> 2, RBINS - 1);
        const int t = o & 3;
        const int s = (k * Lw) / RBINS;
        const int e = ((k + 1) * Lw + RBINS - 1) / RBINS;
        g_wsrc[n * 32 + o] = c0[2] + min(s + t, e - 1);
    }

    if (o < nrows) {                 // row plan
        const int d = o / Lh;
        const int h = o - d * Lh;
        const int src = (c0[0] + d) * (FDIM * FDIM) + (c0[1] + h) * FDIM; // 15b
        const int dst = d * PD + h * PH;                                  // 11b
        g_rows[n * MAXROWS + o] = src | (dst << 16);
    }

    if (o < NBINS) {                 // phase-2 bin descriptors
        const int k = o % RBINS;
        const int j = (o / RBINS) % RBINS;
        const int i = o / (RBINS * RBINS);

        const int ds = (i * Ld) / RBINS, de = ((i + 1) * Ld + RBINS - 1) / RBINS;
        const int hs = (j * Lh) / RBINS, he = ((j + 1) * Lh + RBINS - 1) / RBINS;

        const int start = ds * PD + hs * PH + k;        // <= 1371, 11 bits
        g_desc[n * NBINS + o] =
            start | ((de - ds - 1) << 11) | ((he - hs - 1) << 13);
    }
}

__global__ __launch_bounds__(352)
void pool_kernel(const float* __restrict__ f, float* __restrict__ out)
{
    const int n  = blockIdx.x;          // proposal
    const int cg = blockIdx.y * CH;     // first channel of this block
    const int tid  = threadIdx.x;
    const int lane = tid & 31;
    const int wid  = tid >> 5;          // 0..10

    __shared__ float pyr[CH * PC];      // 8 * 1372 * 4B = 43904 B

    const int2 meta = g_meta[n];
    const float* src0 = f + meta.x + (cg << 15);

    const int  wsrc = g_wsrc[n * 32 + lane];
    const int  kk   = lane >> 2;
    const bool wr   = ((lane & 3) == 0) && (lane < 28);

    // this warp's row plan, one row per lane (rows wid, wid+11, ...)
    const int plan = g_rows[n * MAXROWS + min(wid + lane * 11, MAXROWS - 1)];
    const int nit  = (meta.y - wid + 10) / 11;

    for (int it = 0; it < nit; ++it) {
        const int rd = __shfl_sync(0xFFFFFFFFu, plan, it);
        const float* r = src0 + (rd & 0xFFFF) + wsrc;
        const int dst = (rd >> 16) + kk;
#pragma unroll
        for (int c = 0; c < CH; ++c) {
            float v = r[c << 15];                       // 1 line -> 1 wavefront
            v = fmaxf(v, __shfl_xor_sync(0xFFFFFFFFu, v, 1));
            v = fmaxf(v, __shfl_xor_sync(0xFFFFFFFFu, v, 2));
            if (wr) pyr[c * PC + dst] = v;              // 7 consecutive words
        }
    }
    __syncthreads();

    if (tid < NBINS) {
        const int dsc = g_desc[n * NBINS + tid];
        const int st =  dsc        & 0x7FF;
        const int nd = (dsc >> 11) & 3;
        const int nh = (dsc >> 13) & 3;

        float* op = out + (size_t)(n * 64 + cg) * NBINS + tid;
#pragma unroll
        for (int c = 0; c < CH; ++c) {
            const float* pb = pyr + c * PC + st;
            float m = -FLT_MAX;
            for (int d = 0; d <= nd; ++d)
                for (int h = 0; h <= nh; ++h)
                    m = fmaxf(m, pb[d * PD + h * PH]);
            op[c * NBINS] = m;                           // coalesced
        }
    }
}

extern "C" void kernel_launch(void* const* d_in, const int* in_sizes, int n_in,
                              void* d_out, int out_size)
{
    const float* f     = (const float*)d_in[0];
    const float* props = (const float*)d_in[2];
    float* out = (float*)d_out;

    const int N = in_sizes[2] / 8;   // 96

    precompute_kernel<<<N, 352>>>(props);
    pool_kernel<<<dim3(N, 64 / CH), 352>>>(f, out);
}